// round 1
// baseline (speedup 1.0000x reference)
#include <cuda_runtime.h>
#include <math.h>

// Problem constants (fixed by setup_inputs)
#define BSZ   16
#define QN    900
#define CN    80
#define TN    1600
#define GS    3
#define NQ    (BSZ * QN)        // 14400
#define NROWS (NQ / GS)         // 4800 output rows
#define RPB   (QN / GS)         // 300 rows per batch

// Scratch (allocation-free rule: __device__ globals)
__device__ float  g_cc[NQ * CN];            // focal class cost table [N, C]
__device__ float4 g_qd[NQ * 3];             // per-query: [cx,cy,w,h][x0,y0,x1,y1][area,-,-,-]
__device__ float4 g_td[TN * 3];             // per-target: [cx,cy,w,h][x0,y0,x1,y1][area,label,-,-]

// ---------------- prep: focal classification cost table ----------------
__global__ void prep_cc_kernel(const float* __restrict__ logits) {
    int i = blockIdx.x * 256 + threadIdx.x;          // NQ*CN = 1,152,000 (exact multiple of 256)
    float x = logits[i];
    float p = 1.f / (1.f + expf(-x));
    float neg = 0.75f * p * p * (-logf(1.f - p + 1e-8f));
    float pos = 0.25f * (1.f - p) * (1.f - p) * (-logf(p + 1e-8f));
    g_cc[i] = pos - neg;
}

// ---------------- prep: box structs for queries and targets ----------------
__global__ void prep_box_kernel(const float* __restrict__ qb,
                                const float* __restrict__ tb,
                                const int*   __restrict__ tl) {
    int i = blockIdx.x * 256 + threadIdx.x;
    if (i < NQ) {
        float cx = qb[i*4+0], cy = qb[i*4+1], w = qb[i*4+2], h = qb[i*4+3];
        float x0 = cx - 0.5f*w, y0 = cy - 0.5f*h;
        float x1 = cx + 0.5f*w, y1 = cy + 0.5f*h;
        float area = (x1 - x0) * (y1 - y0);          // match reference op order
        g_qd[i*3+0] = make_float4(cx, cy, w, h);
        g_qd[i*3+1] = make_float4(x0, y0, x1, y1);
        g_qd[i*3+2] = make_float4(area, 0.f, 0.f, 0.f);
    }
    if (i < TN) {
        float cx = tb[i*4+0], cy = tb[i*4+1], w = tb[i*4+2], h = tb[i*4+3];
        float x0 = cx - 0.5f*w, y0 = cy - 0.5f*h;
        float x1 = cx + 0.5f*w, y1 = cy + 0.5f*h;
        float area = (x1 - x0) * (y1 - y0);
        g_td[i*3+0] = make_float4(cx, cy, w, h);
        g_td[i*3+1] = make_float4(x0, y0, x1, y1);
        g_td[i*3+2] = make_float4(area, __int_as_float(tl[i]), 0.f, 0.f);
    }
}

// ---------------- main: fused cost + group-max ----------------
#define THR  320     // 1600 / 5 col-tiles; 10 warps
#define RCH  50      // output rows per block chunk (300 % 50 == 0 -> no batch crossing)

__global__ __launch_bounds__(THR) void cost_kernel(float* __restrict__ out) {
    __shared__ float4 shq[RCH * 3 * 3];              // 50 rows x 3 queries x 3 float4 = 7.2 KB

    const int t  = blockIdx.x * THR + threadIdx.x;   // target column, always < 1600
    const int r0 = blockIdx.y * RCH;                 // first output row of this chunk
    const int nstart = (r0 / RPB) * QN + (r0 % RPB) * GS;  // first query index (150 consecutive)

    // cooperative stage of 150 consecutive query structs
    const float4* src = g_qd + nstart * 3;
    #pragma unroll
    for (int i = threadIdx.x; i < RCH * 9; i += THR) shq[i] = src[i];
    __syncthreads();

    // target data -> registers (held for the whole chunk)
    const float4 tA = g_td[t*3+0];
    const float4 tB = g_td[t*3+1];
    const float4 tC = g_td[t*3+2];
    const float  tarea = tC.x;
    const int    lab   = __float_as_int(tC.y);
    const float* ccp   = g_cc + lab;

    float* op = out + (size_t)r0 * TN + t;
    int nb = nstart;

    for (int rr = 0; rr < RCH; rr++, nb += GS) {
        float m = __int_as_float(0xff800000);        // -inf
        #pragma unroll
        for (int g = 0; g < GS; g++) {
            const float4 qA = shq[(rr*3 + g)*3 + 0];
            const float4 qB = shq[(rr*3 + g)*3 + 1];
            const float  qarea = shq[(rr*3 + g)*3 + 2].x;
            const float  cc = __ldg(ccp + (nb + g) * CN);   // L2-resident gather

            // L1 box cost (cxcywh)
            float l1 = fabsf(qA.x - tA.x) + fabsf(qA.y - tA.y)
                     + fabsf(qA.z - tA.z) + fabsf(qA.w - tA.w);

            // intersection
            float ltx = fmaxf(qB.x, tB.x), lty = fmaxf(qB.y, tB.y);
            float rbx = fminf(qB.z, tB.z), rby = fminf(qB.w, tB.w);
            float wx = fmaxf(rbx - ltx, 0.f), wy = fmaxf(rby - lty, 0.f);
            float inter = wx * wy;
            float uni = qarea + tarea - inter;

            // enclosing box
            float ex0 = fminf(qB.x, tB.x), ey0 = fminf(qB.y, tB.y);
            float ex1 = fmaxf(qB.z, tB.z), ey1 = fmaxf(qB.w, tB.w);
            float earea = (ex1 - ex0) * (ey1 - ey0);

            // cost = 5*L1 + 2*cc + 2*(earea-uni)/earea - 2*inter/uni
            float ru = __fdividef(1.f, uni);
            float re = __fdividef(1.f, earea);
            float gterm = __fmaf_rn(-2.f * uni, re, 2.f);
            gterm = __fmaf_rn(-2.f * inter, ru, gterm);
            float cost = __fmaf_rn(5.f, l1, __fmaf_rn(2.f, cc, gterm));
            m = fmaxf(m, cost);
        }
        *op = m;
        op += TN;
    }
}

extern "C" void kernel_launch(void* const* d_in, const int* in_sizes, int n_in,
                              void* d_out, int out_size) {
    const float* logits  = (const float*)d_in[0];  // [16,900,80]
    const float* pboxes  = (const float*)d_in[1];  // [16,900,4]
    const int*   tlabels = (const int*)  d_in[2];  // [1600]
    const float* tboxes  = (const float*)d_in[3];  // [1600,4]
    // d_in[4] = g_size (== 3, compiled in)
    (void)in_sizes; (void)n_in; (void)out_size;

    prep_cc_kernel<<<(NQ * CN) / 256, 256>>>(logits);
    prep_box_kernel<<<(NQ + 255) / 256, 256>>>(pboxes, tboxes, tlabels);
    cost_kernel<<<dim3(TN / THR, NROWS / RCH), THR>>>((float*)d_out);
}

// round 2
// speedup vs baseline: 1.1800x; 1.1800x over previous
#include <cuda_runtime.h>
#include <math.h>

// Problem constants (fixed by setup_inputs)
#define BSZ   16
#define QN    900
#define CN    80
#define TN    1600
#define GS    3
#define NQ    (BSZ * QN)        // 14400
#define NROWS (NQ / GS)         // 4800 output rows
#define RPB   (QN / GS)         // 300 rows per batch

// Scratch (allocation-free rule: __device__ globals)
__device__ float  g_cc[NQ * CN];            // focal class cost table [N, C]
__device__ float4 g_qd[NQ * 3];             // per-query: [cx,cy,w,h][x0,y0,x1,y1][area,-,-,-]
__device__ float4 g_td[TN * 3];             // per-target: [cx,cy,w,h][x0,y0,x1,y1][area,label,-,-]

__device__ __forceinline__ float focal_cc(float x) {
    float p   = 1.f / (1.f + __expf(-x));
    float om  = 1.f - p;
    float pos = 0.25f * om * om * (-__logf(p + 1e-8f));
    float neg = 0.75f * p  * p  * (-__logf(om + 1e-8f));
    return pos - neg;
}

// ---------------- fused prep: focal table (float4) + box structs ----------------
#define CCB 1125   // (NQ*CN/4)/256 blocks for the cc table
#define BXB 57     // ceil(NQ/256) blocks for boxes

__global__ __launch_bounds__(256) void prep_kernel(const float4* __restrict__ logits4,
                                                   const float*  __restrict__ qb,
                                                   const float*  __restrict__ tb,
                                                   const int*    __restrict__ tl) {
    int b = blockIdx.x;
    if (b < CCB) {
        int i = b * 256 + threadIdx.x;
        float4 x = logits4[i];
        float4 r;
        r.x = focal_cc(x.x); r.y = focal_cc(x.y);
        r.z = focal_cc(x.z); r.w = focal_cc(x.w);
        reinterpret_cast<float4*>(g_cc)[i] = r;
    } else {
        int i = (b - CCB) * 256 + threadIdx.x;
        if (i < NQ) {
            float cx = qb[i*4+0], cy = qb[i*4+1], w = qb[i*4+2], h = qb[i*4+3];
            float x0 = cx - 0.5f*w, y0 = cy - 0.5f*h;
            float x1 = cx + 0.5f*w, y1 = cy + 0.5f*h;
            float area = (x1 - x0) * (y1 - y0);
            g_qd[i*3+0] = make_float4(cx, cy, w, h);
            g_qd[i*3+1] = make_float4(x0, y0, x1, y1);
            g_qd[i*3+2] = make_float4(area, 0.f, 0.f, 0.f);
        }
        if (i < TN) {
            float cx = tb[i*4+0], cy = tb[i*4+1], w = tb[i*4+2], h = tb[i*4+3];
            float x0 = cx - 0.5f*w, y0 = cy - 0.5f*h;
            float x1 = cx + 0.5f*w, y1 = cy + 0.5f*h;
            float area = (x1 - x0) * (y1 - y0);
            g_td[i*3+0] = make_float4(cx, cy, w, h);
            g_td[i*3+1] = make_float4(x0, y0, x1, y1);
            g_td[i*3+2] = make_float4(area, __int_as_float(tl[i]), 0.f, 0.f);
        }
    }
}

// ---------------- main: fused cost + group-max ----------------
#define THR  320     // 1600 / 5 col-tiles; 10 warps
#define RCH  15      // output rows per block chunk (300 % 15 == 0; grid = 5 x 320 = 1600 blocks)

__device__ __forceinline__ float rcp_approx(float x) {
    float r;
    asm("rcp.approx.f32 %0, %1;" : "=f"(r) : "f"(x));
    return r;
}

__global__ __launch_bounds__(THR) void cost_kernel(float* __restrict__ out) {
    __shared__ float4 shq[RCH * 3 * 3];              // 15 rows x 3 queries x 3 float4 = 2.16 KB

    const int t  = blockIdx.x * THR + threadIdx.x;   // target column, always < 1600
    const int r0 = blockIdx.y * RCH;                 // first output row of this chunk
    const int nstart = (r0 / RPB) * QN + (r0 % RPB) * GS;  // first query index (45 consecutive)

    // cooperative stage of 45 consecutive query structs
    if (threadIdx.x < RCH * 9) shq[threadIdx.x] = g_qd[nstart * 3 + threadIdx.x];
    __syncthreads();

    // target data -> registers (held for the whole chunk)
    const float4 tA = g_td[t*3+0];
    const float4 tB = g_td[t*3+1];
    const float4 tC = g_td[t*3+2];
    const float  tarea = tC.x;
    const int    lab   = __float_as_int(tC.y);
    const float* ccp   = g_cc + lab;

    float* op = out + (size_t)r0 * TN + t;
    int nb = nstart;

    for (int rr = 0; rr < RCH; rr++, nb += GS) {
        float c[GS];
        #pragma unroll
        for (int g = 0; g < GS; g++) {
            const float4 qA = shq[(rr*3 + g)*3 + 0];
            const float4 qB = shq[(rr*3 + g)*3 + 1];
            const float  qarea = shq[(rr*3 + g)*3 + 2].x;
            const float  cc = __ldg(ccp + (nb + g) * CN);   // L2-resident gather

            // L1 box cost (cxcywh)
            float l1 = fabsf(qA.x - tA.x) + fabsf(qA.y - tA.y)
                     + fabsf(qA.z - tA.z) + fabsf(qA.w - tA.w);

            // intersection
            float ltx = fmaxf(qB.x, tB.x), lty = fmaxf(qB.y, tB.y);
            float rbx = fminf(qB.z, tB.z), rby = fminf(qB.w, tB.w);
            float wx = fmaxf(rbx - ltx, 0.f), wy = fmaxf(rby - lty, 0.f);
            float inter = wx * wy;
            float uni = qarea + tarea - inter;

            // enclosing box
            float ex0 = fminf(qB.x, tB.x), ey0 = fminf(qB.y, tB.y);
            float ex1 = fmaxf(qB.z, tB.z), ey1 = fmaxf(qB.w, tB.w);
            float earea = (ex1 - ex0) * (ey1 - ey0);

            // cost = 5*l1 + 2*cc + 2*(1 - uni/earea - inter/uni)
            float ru = rcp_approx(uni);
            float re = rcp_approx(earea);
            float s  = __fmaf_rn(-uni,   re, 1.0f);
            s        = __fmaf_rn(-inter, ru, s);
            c[g] = __fmaf_rn(2.f, s, __fmaf_rn(5.f, l1, cc + cc));
        }
        *op = fmaxf(fmaxf(c[0], c[1]), c[2]);
        op += TN;
    }
}

extern "C" void kernel_launch(void* const* d_in, const int* in_sizes, int n_in,
                              void* d_out, int out_size) {
    const float* logits  = (const float*)d_in[0];  // [16,900,80]
    const float* pboxes  = (const float*)d_in[1];  // [16,900,4]
    const int*   tlabels = (const int*)  d_in[2];  // [1600]
    const float* tboxes  = (const float*)d_in[3];  // [1600,4]
    (void)in_sizes; (void)n_in; (void)out_size;

    prep_kernel<<<CCB + BXB, 256>>>((const float4*)logits, pboxes, tboxes, tlabels);
    cost_kernel<<<dim3(TN / THR, NROWS / RCH), THR>>>((float*)d_out);
}

// round 3
// speedup vs baseline: 1.3958x; 1.1829x over previous
#include <cuda_runtime.h>
#include <math.h>

// Problem constants (fixed by setup_inputs)
#define BSZ   16
#define QN    900
#define CN    80
#define TN    1600
#define GS    3
#define NQ    (BSZ * QN)        // 14400
#define NROWS (NQ / GS)         // 4800 output rows
#define RPB   (QN / GS)         // 300 rows per batch

// Scratch (allocation-free rule: __device__ globals)
__device__ float  g_cc[NQ * CN];            // 2x focal class cost table [N, C]
__device__ float4 g_qd[NQ * 3];             // per-query:  [5cx,5cy,5w,5h][x0,y0,x1,y1][area,w,h,-]
__device__ float4 g_td[TN * 3];             // per-target: [5cx,5cy,5w,5h][x0,y0,x1,y1][area,w,h,label]

__device__ __forceinline__ float focal_cc2(float x) {
    float p   = 1.f / (1.f + __expf(-x));
    float om  = 1.f - p;
    float pos = 0.5f * om * om * (-__logf(p + 1e-8f));   // 2 * 0.25
    float neg = 1.5f * p  * p  * (-__logf(om + 1e-8f));  // 2 * 0.75
    return pos - neg;
}

// ---------------- fused prep ----------------
#define CCB 1125   // (NQ*CN/4)/256 blocks for the cc table
#define BXB 57     // ceil(NQ/256) blocks for boxes

__global__ __launch_bounds__(256) void prep_kernel(const float4* __restrict__ logits4,
                                                   const float*  __restrict__ qb,
                                                   const float*  __restrict__ tb,
                                                   const int*    __restrict__ tl) {
    int b = blockIdx.x;
    if (b < CCB) {
        int i = b * 256 + threadIdx.x;
        float4 x = logits4[i];
        float4 r;
        r.x = focal_cc2(x.x); r.y = focal_cc2(x.y);
        r.z = focal_cc2(x.z); r.w = focal_cc2(x.w);
        reinterpret_cast<float4*>(g_cc)[i] = r;
    } else {
        int i = (b - CCB) * 256 + threadIdx.x;
        if (i < NQ) {
            float cx = qb[i*4+0], cy = qb[i*4+1], w = qb[i*4+2], h = qb[i*4+3];
            float x0 = cx - 0.5f*w, y0 = cy - 0.5f*h;
            float x1 = cx + 0.5f*w, y1 = cy + 0.5f*h;
            float ww = x1 - x0, hh = y1 - y0;
            float area = ww * hh;                       // same rounding path as reference
            g_qd[i*3+0] = make_float4(5.f*cx, 5.f*cy, 5.f*w, 5.f*h);
            g_qd[i*3+1] = make_float4(x0, y0, x1, y1);
            g_qd[i*3+2] = make_float4(area, ww, hh, 0.f);
        }
        if (i < TN) {
            float cx = tb[i*4+0], cy = tb[i*4+1], w = tb[i*4+2], h = tb[i*4+3];
            float x0 = cx - 0.5f*w, y0 = cy - 0.5f*h;
            float x1 = cx + 0.5f*w, y1 = cy + 0.5f*h;
            float ww = x1 - x0, hh = y1 - y0;
            float area = ww * hh;
            g_td[i*3+0] = make_float4(5.f*cx, 5.f*cy, 5.f*w, 5.f*h);
            g_td[i*3+1] = make_float4(x0, y0, x1, y1);
            g_td[i*3+2] = make_float4(area, ww, hh, __int_as_float(tl[i]));
        }
    }
}

// ---------------- main: fused cost + group-max, 2 columns per thread ----------------
#define THR  160     // 5 warps; thread covers columns t and t+800
#define RCH  10      // output rows per block (300 % 10 == 0; grid = 5 x 480 = 2400 blocks)

__device__ __forceinline__ float rcp_approx(float x) {
    float r;
    asm("rcp.approx.f32 %0, %1;" : "=f"(r) : "f"(x));
    return r;
}

__device__ __forceinline__ float pair_cost(const float4 qA, const float4 qB, const float4 qC,
                                           const float4 tA, const float4 tB, const float4 tC,
                                           const float cc2) {
    // L1 box cost (inputs pre-scaled by 5)
    float l1 = fabsf(qA.x - tA.x) + fabsf(qA.y - tA.y)
             + fabsf(qA.z - tA.z) + fabsf(qA.w - tA.w);
    // intersection
    float ltx = fmaxf(qB.x, tB.x), lty = fmaxf(qB.y, tB.y);
    float rbx = fminf(qB.z, tB.z), rby = fminf(qB.w, tB.w);
    float dx = rbx - ltx,          dy = rby - lty;
    float wx = fmaxf(dx, 0.f),     wy = fmaxf(dy, 0.f);
    float inter = wx * wy;
    float uni = (qC.x + tC.x) - inter;
    // enclosing box via max(a,b) = a+b-min(a,b):  ewx = qw + tw - dx
    float ewx = (qC.y + tC.y) - dx;
    float ewy = (qC.z + tC.z) - dy;
    float earea = ewx * ewy;
    // cost = l1(x5) + cc(x2) + 2*(1 - uni/earea - inter/uni)
    float ru = rcp_approx(uni);
    float re = rcp_approx(earea);
    float s  = __fmaf_rn(-uni,   re, 1.0f);
    s        = __fmaf_rn(-inter, ru, s);
    return __fmaf_rn(2.f, s, l1 + cc2);
}

__global__ __launch_bounds__(THR) void cost_kernel(float* __restrict__ out) {
    __shared__ float4 shq[RCH * 3 * 3];              // 30 queries x 3 float4 = 1.44 KB

    const int t0 = blockIdx.x * THR + threadIdx.x;   // first target column (< 800)
    const int t1 = t0 + 800;                         // second target column
    const int r0 = blockIdx.y * RCH;                 // first output row of this chunk
    const int nstart = (r0 / RPB) * QN + (r0 % RPB) * GS;

    if (threadIdx.x < RCH * 9) shq[threadIdx.x] = g_qd[nstart * 3 + threadIdx.x];
    __syncthreads();

    // target data -> registers (held for the whole chunk)
    const float4 tA0 = g_td[t0*3+0], tB0 = g_td[t0*3+1], tC0 = g_td[t0*3+2];
    const float4 tA1 = g_td[t1*3+0], tB1 = g_td[t1*3+1], tC1 = g_td[t1*3+2];
    const float* ccp0 = g_cc + nstart * CN + __float_as_int(tC0.w);
    const float* ccp1 = g_cc + nstart * CN + __float_as_int(tC1.w);

    float* op = out + (size_t)r0 * TN + t0;

    #pragma unroll 2
    for (int rr = 0; rr < RCH; rr++) {
        float m0, m1;
        #pragma unroll
        for (int g = 0; g < GS; g++) {
            const float4 qA = shq[(rr*3 + g)*3 + 0];
            const float4 qB = shq[(rr*3 + g)*3 + 1];
            const float4 qC = shq[(rr*3 + g)*3 + 2];
            const float cc0 = __ldg(ccp0 + g * CN);
            const float cc1 = __ldg(ccp1 + g * CN);
            float c0 = pair_cost(qA, qB, qC, tA0, tB0, tC0, cc0);
            float c1 = pair_cost(qA, qB, qC, tA1, tB1, tC1, cc1);
            if (g == 0) { m0 = c0; m1 = c1; }
            else        { m0 = fmaxf(m0, c0); m1 = fmaxf(m1, c1); }
        }
        op[0]   = m0;
        op[800] = m1;
        op += TN;
        ccp0 += GS * CN;
        ccp1 += GS * CN;
    }
}

extern "C" void kernel_launch(void* const* d_in, const int* in_sizes, int n_in,
                              void* d_out, int out_size) {
    const float* logits  = (const float*)d_in[0];  // [16,900,80]
    const float* pboxes  = (const float*)d_in[1];  // [16,900,4]
    const int*   tlabels = (const int*)  d_in[2];  // [1600]
    const float* tboxes  = (const float*)d_in[3];  // [1600,4]
    (void)in_sizes; (void)n_in; (void)out_size;

    prep_kernel<<<CCB + BXB, 256>>>((const float4*)logits, pboxes, tboxes, tlabels);
    cost_kernel<<<dim3(800 / THR, NROWS / RCH), THR>>>((float*)d_out);
}